// round 3
// baseline (speedup 1.0000x reference)
#include <cuda_runtime.h>
#include <cuda_bf16.h>

// Problem shapes (fixed by the dataset)
#define Bsz 128
#define Tsz 32
#define Dsz 6400
#define Hsz 1000
#define Asz 4

#define Msz (Bsz * Tsz)   // 4096 rows of the big GEMM

// Scratch: h1[m][h] = x_flat[m] . W1[h] + b1[h]   (16.38 MB, static device array)
__device__ float g_h1[Msz * Hsz];

// ---------------------------------------------------------------------------
// Kernel A: fp32 SGEMM, C[M,N] = A[M,K] . B[N,K]^T + bias  (both K-major)
// BM=128, BN=64, BK=16, 256 threads, 8x4 micro-tile per thread.
// Register-prefetch double buffering: next tile's LDGs issued before the
// current tile's FFMA block so DRAM/L2 latency overlaps compute.
// Sequential-K accumulation (matches reference dot-product order closely).
// ---------------------------------------------------------------------------
#define BM 128
#define BN 64
#define BK 16

__global__ __launch_bounds__(256, 2)
void gemm_h1_kernel(const float* __restrict__ A,    // x  [4096, 6400]
                    const float* __restrict__ B,    // W1 [1000, 6400]
                    const float* __restrict__ bias) // b1 [1000]
{
    __shared__ float As[BK][BM + 4];
    __shared__ float Bs[BK][BN + 4];

    const int tid = threadIdx.x;
    const int bm  = blockIdx.y;     // 0..31
    const int bn  = blockIdx.x;     // 0..15
    const int tx  = tid & 15;       // N direction (x4)
    const int ty  = tid >> 4;       // M direction (x8)

    float acc[8][4];
#pragma unroll
    for (int i = 0; i < 8; i++)
#pragma unroll
        for (int j = 0; j < 4; j++) acc[i][j] = 0.0f;

    const int lrow = tid >> 2;            // 0..63
    const int kq   = (tid & 3) * 4;       // 0,4,8,12

    const int arow0 = bm * BM + lrow;
    const int arow1 = arow0 + 64;
    const int bgr   = bn * BN + lrow;
    const bool bvalid = (bgr < Hsz);

    const float* Ap0 = A + (size_t)arow0 * Dsz + kq;
    const float* Ap1 = A + (size_t)arow1 * Dsz + kq;
    const float* Bp  = B + (size_t)(bvalid ? bgr : 0) * Dsz + kq;

    // prologue: load first tile into registers
    float4 a0 = *(const float4*)(Ap0);
    float4 a1 = *(const float4*)(Ap1);
    float4 b0 = bvalid ? *(const float4*)(Bp)
                       : make_float4(0.f, 0.f, 0.f, 0.f);

    for (int kt = 0; kt < Dsz; kt += BK) {
        // stage current tile to smem
        As[kq + 0][lrow] = a0.x;  As[kq + 1][lrow] = a0.y;
        As[kq + 2][lrow] = a0.z;  As[kq + 3][lrow] = a0.w;
        As[kq + 0][lrow + 64] = a1.x;  As[kq + 1][lrow + 64] = a1.y;
        As[kq + 2][lrow + 64] = a1.z;  As[kq + 3][lrow + 64] = a1.w;
        Bs[kq + 0][lrow] = b0.x;  Bs[kq + 1][lrow] = b0.y;
        Bs[kq + 2][lrow] = b0.z;  Bs[kq + 3][lrow] = b0.w;

        __syncthreads();

        // prefetch next tile (overlaps with FFMA block below)
        const int knext = kt + BK;
        if (knext < Dsz) {
            a0 = *(const float4*)(Ap0 + knext);
            a1 = *(const float4*)(Ap1 + knext);
            b0 = bvalid ? *(const float4*)(Bp + knext)
                        : make_float4(0.f, 0.f, 0.f, 0.f);
        }

#pragma unroll
        for (int k = 0; k < BK; k++) {
            float av[8], bv[4];
#pragma unroll
            for (int i = 0; i < 8; i++) av[i] = As[k][ty * 8 + i];
#pragma unroll
            for (int j = 0; j < 4; j++) bv[j] = Bs[k][tx * 4 + j];
#pragma unroll
            for (int i = 0; i < 8; i++)
#pragma unroll
                for (int j = 0; j < 4; j++)
                    acc[i][j] = fmaf(av[i], bv[j], acc[i][j]);
        }
        __syncthreads();
    }

    const int row0 = bm * BM + ty * 8;
    const int col0 = bn * BN + tx * 4;
#pragma unroll
    for (int j = 0; j < 4; j++) {
        const int c = col0 + j;
        if (c < Hsz) {
            const float bv = bias[c];
#pragma unroll
            for (int i = 0; i < 8; i++)
                g_h1[(size_t)(row0 + i) * Hsz + c] = acc[i][j] + bv;
        }
    }
}

// ---------------------------------------------------------------------------
// Kernel B: LIF recurrence. One block per batch element; mem1 state in
// registers (4 h's per thread), W2 staged in smem, per-step block reduction
// for the tiny second layer, mem2 held by threads 0..3.
// ---------------------------------------------------------------------------
__global__ __launch_bounds__(256, 1)
void snn_recurrence_kernel(const float* __restrict__ W2,   // [4, 1000]
                           const float* __restrict__ b2,   // [4]
                           float* __restrict__ out)        // [128, 32, 4]
{
    __shared__ float sW2[Asz * Hsz];
    __shared__ float red[8][4];

    const int b   = blockIdx.x;
    const int tid = threadIdx.x;

    for (int i = tid; i < Asz * Hsz; i += 256) sW2[i] = W2[i];

    float mem1[4] = {0.f, 0.f, 0.f, 0.f};
    float mem2 = 0.f;
    const float b2v = (tid < Asz) ? b2[tid] : 0.f;

    __syncthreads();

    for (int t = 0; t < Tsz; t++) {
        const float* h1row = g_h1 + (size_t)(b * Tsz + t) * Hsz;
        float acc[4] = {0.f, 0.f, 0.f, 0.f};

#pragma unroll
        for (int j = 0; j < 4; j++) {
            const int h = tid + j * 256;
            if (h < Hsz) {
                const float cur   = h1row[h];
                const float m     = mem1[j];
                // reset based on PREVIOUS mem crossing threshold
                const float keep  = (m > 1.0f) ? 0.f : 1.f;
                const float mnew  = (0.99f * m + cur) * keep;
                mem1[j] = mnew;
                if (mnew - 1.0f > 0.f) {   // spike == 1
                    acc[0] += sW2[h];
                    acc[1] += sW2[Hsz + h];
                    acc[2] += sW2[2 * Hsz + h];
                    acc[3] += sW2[3 * Hsz + h];
                }
            }
        }

        // warp reduce, then cross-warp via smem
#pragma unroll
        for (int a = 0; a < 4; a++)
#pragma unroll
            for (int off = 16; off > 0; off >>= 1)
                acc[a] += __shfl_down_sync(0xffffffffu, acc[a], off);

        const int warp = tid >> 5;
        if ((tid & 31) == 0) {
            red[warp][0] = acc[0];
            red[warp][1] = acc[1];
            red[warp][2] = acc[2];
            red[warp][3] = acc[3];
        }
        __syncthreads();

        if (tid < Asz) {
            float s = b2v;
#pragma unroll
            for (int w = 0; w < 8; w++) s += red[w][tid];
            const float m    = mem2;
            const float keep = (m > 1.0f) ? 0.f : 1.f;
            const float mnew = (0.99f * m + s) * keep;
            mem2 = mnew;
            out[(size_t)(b * Tsz + t) * Asz + tid] = (mnew - 1.0f > 0.f) ? 1.0f : 0.f;
        }
        __syncthreads();
    }
}

// ---------------------------------------------------------------------------
extern "C" void kernel_launch(void* const* d_in, const int* in_sizes, int n_in,
                              void* d_out, int out_size)
{
    const float* x  = (const float*)d_in[0];   // [128, 32, 6400]
    const float* W1 = (const float*)d_in[1];   // [1000, 6400]
    const float* b1 = (const float*)d_in[2];   // [1000]
    const float* W2 = (const float*)d_in[3];   // [4, 1000]
    const float* b2 = (const float*)d_in[4];   // [4]
    float* out = (float*)d_out;                // [128, 32, 4]

    (void)in_sizes; (void)n_in; (void)out_size;

    dim3 ggrid((Hsz + BN - 1) / BN, Msz / BM);   // (16, 32)
    gemm_h1_kernel<<<ggrid, 256>>>(x, W1, b1);

    snn_recurrence_kernel<<<Bsz, 256>>>(W2, b2, out);
}